// round 7
// baseline (speedup 1.0000x reference)
#include <cuda_runtime.h>

#define NI    9
#define NM3   165     // # monomials of degree 3 (i<=j<=l)
#define NM2   45      // # monomials of degree 2 (i<=j)
#define ST3   32      // padded deg-3 column stride (23 or 30 -> 32)
#define CDIM  256
#define EDIM  10

typedef unsigned long long ull;

// Symmetrized, padded U tables. pass 0 = scalar channel, pass 1..3 = vector a=0..2.
__device__ __align__(16) float g_T3[4][NM3 * ST3];
__device__ __align__(16) float g_T2[4][NM2 * 4];

__device__ __forceinline__ void decode3(int m, int& i, int& j, int& l) {
    int cnt = 0;
    for (int a = 0; a < NI; a++)
        for (int b = a; b < NI; b++)
            for (int c = b; c < NI; c++) {
                if (cnt == m) { i = a; j = b; l = c; return; }
                cnt++;
            }
    i = j = l = 0;
}

__device__ __forceinline__ void decode2(int m, int& i, int& j) {
    int cnt = 0;
    for (int a = 0; a < NI; a++)
        for (int b = a; b < NI; b++) {
            if (cnt == m) { i = a; j = b; return; }
            cnt++;
        }
    i = j = 0;
}

__global__ void precompute_kernel(const float* __restrict__ U2s,
                                  const float* __restrict__ U3s,
                                  const float* __restrict__ U2v,
                                  const float* __restrict__ U3v) {
    int t = blockIdx.x * blockDim.x + threadIdx.x;
    const int N3 = 4 * NM3 * ST3;
    const int N2 = 4 * NM2 * 4;
    if (t < N3) {
        int pass = t / (NM3 * ST3);
        int r = t % (NM3 * ST3);
        int m = r / ST3, k = r % ST3;
        int K = (pass == 0) ? 23 : 30;
        float val = 0.f;
        if (k < K) {
            int i, j, l;
            decode3(m, i, j, l);
            int pi[6] = { i, i, j, j, l, l };
            int pj[6] = { j, l, i, l, i, j };
            int pl[6] = { l, j, l, i, j, i };
            const float* base = (pass == 0) ? U3s : (U3v + (pass - 1) * (NI * NI * NI * 30));
            int codes[6];
            for (int p = 0; p < 6; p++) {
                int code = (pi[p] * NI + pj[p]) * NI + pl[p];
                bool dup = false;
                for (int q = 0; q < p; q++)
                    if (codes[q] == code) dup = true;
                codes[p] = code;
                if (!dup) val += base[code * K + k];
            }
        }
        g_T3[pass][m * ST3 + k] = val;
    } else if (t < N3 + N2) {
        int u = t - N3;
        int pass = u / (NM2 * 4);
        int r = u % (NM2 * 4);
        int m = r / 4, k = r % 4;
        int K = (pass == 0) ? 3 : 4;
        float val = 0.f;
        if (k < K) {
            int i, j;
            decode2(m, i, j);
            const float* base = (pass == 0) ? U2s : (U2v + (pass - 1) * (NI * NI * 4));
            val = base[(i * NI + j) * K + k];
            if (i != j) val += base[(j * NI + i) * K + k];
        }
        g_T2[pass][m * 4 + k] = val;
    }
}

// ---- packed f32x2 helpers ----
__device__ __forceinline__ ull pack2(float x) {
    ull r; asm("mov.b64 %0, {%1, %1};" : "=l"(r) : "f"(x)); return r;
}
__device__ __forceinline__ void fma2(ull& d, ull a, ull b) {
    asm("fma.rn.f32x2 %0, %1, %2, %0;" : "+l"(d) : "l"(a), "l"(b));
}
__device__ __forceinline__ void unpack2(ull v, float& lo, float& hi) {
    asm("mov.b64 {%0, %1}, %2;" : "=f"(lo), "=f"(hi) : "l"(v));
}

// Monomial sweep, fully unrolled triangular nest, ONE batch.
// Constexpr indices: every smem address constant-folds; ptxas pipelines the
// LDS.128 table loads across monomials. x lives in 9 registers.
template <int NQ>
__device__ __forceinline__ void sweep(const float* __restrict__ sT3,
                                      const float* __restrict__ sT2,
                                      const float* __restrict__ xr,
                                      ull* __restrict__ acc, ull* __restrict__ a2) {
    const ulonglong2* __restrict__ row  = (const ulonglong2*)sT3;
    const ulonglong2* __restrict__ row2 = (const ulonglong2*)sT2;
    int m3 = 0, m2 = 0;
#pragma unroll
    for (int i = 0; i < NI; i++) {
#pragma unroll
        for (int j = i; j < NI; j++) {
            float xij = xr[i] * xr[j];
            ulonglong2 u2 = row2[m2];
            ull p = pack2(xij);
            fma2(a2[0], u2.x, p);
            fma2(a2[1], u2.y, p);
            m2++;
#pragma unroll
            for (int l = j; l < NI; l++) {
                ull m = pack2(xij * xr[l]);
#pragma unroll
                for (int q = 0; q < NQ; q++) {
                    ulonglong2 t = row[m3 * (ST3 / 4) + q];
                    fma2(acc[2 * q],     t.x, m);
                    fma2(acc[2 * q + 1], t.y, m);
                }
                m3++;
            }
        }
    }
}

// Full pass: sweep + epilogue, one batch.
template <int NQ, int K3, int K2>
__device__ __forceinline__ float do_pass(const float* __restrict__ sT3,
                                         const float* __restrict__ sT2,
                                         const float* __restrict__ xr,
                                         const float* __restrict__ sy,
                                         const float* __restrict__ W3,
                                         const float* __restrict__ W2,
                                         const float* __restrict__ W1,
                                         const float* __restrict__ U1,
                                         int c) {
    ull acc[2 * NQ], a2[2];
#pragma unroll
    for (int q = 0; q < 2 * NQ; q++) acc[q] = 0ull;
    a2[0] = a2[1] = 0ull;

    sweep<NQ>(sT3, sT2, xr, acc, a2);

    float r = 0.f;
#pragma unroll
    for (int k = 0; k < K3; k++) {
        float w = 0.f;
#pragma unroll
        for (int e = 0; e < EDIM; e++)
            w = fmaf(W3[(e * K3 + k) * CDIM + c], sy[e], w);
        float lo, hi;
        unpack2(acc[k / 2], lo, hi);
        r = fmaf(w, (k & 1) ? hi : lo, r);
    }
#pragma unroll
    for (int k = 0; k < K2; k++) {
        float w = 0.f;
#pragma unroll
        for (int e = 0; e < EDIM; e++)
            w = fmaf(W2[(e * K2 + k) * CDIM + c], sy[e], w);
        float lo, hi;
        unpack2(a2[k / 2], lo, hi);
        r = fmaf(w, (k & 1) ? hi : lo, r);
    }
    float d1 = 0.f;
#pragma unroll
    for (int i = 0; i < NI; i++) d1 = fmaf(U1[i], xr[i], d1);
    float w1 = 0.f;
#pragma unroll
    for (int e = 0; e < EDIM; e++) w1 = fmaf(W1[e * CDIM + c], sy[e], w1);
    return fmaf(w1, d1, r);
}

__global__ void __launch_bounds__(CDIM, 2)
sc_main_kernel(const float* __restrict__ x, const float* __restrict__ y,
               const float* __restrict__ U1s, const float* __restrict__ U1v,
               const float* __restrict__ W1s, const float* __restrict__ W2s,
               const float* __restrict__ W3s, const float* __restrict__ W1v,
               const float* __restrict__ W2v, const float* __restrict__ W3v,
               float* __restrict__ out) {
    __shared__ __align__(16) float sT3[NM3 * ST3];   // 21.1 KB
    __shared__ __align__(16) float sT2[NM2 * 4];
    __shared__ __align__(16) float sx[CDIM * NI];    // 9.2 KB
    __shared__ float sy[16];

    const int b = blockIdx.x;
    const int c = threadIdx.x;

    {
        const float4* src = (const float4*)(x + (size_t)b * (CDIM * NI));
        float4* dst = (float4*)sx;
        for (int t = c; t < CDIM * NI / 4; t += CDIM) dst[t] = src[t];
        if (c < EDIM) sy[c] = y[b * EDIM + c];
    }
    __syncthreads();

    // x row into registers, reused by all 4 passes (stride-9: conflict-free)
    float xr[NI];
#pragma unroll
    for (int i = 0; i < NI; i++) xr[i] = sx[c * NI + i];

    // ---- pass 0: scalar channel ----
    {
        const float4* s3 = (const float4*)g_T3[0];
        float4* d3 = (float4*)sT3;
        for (int t = c; t < NM3 * ST3 / 4; t += CDIM) d3[t] = s3[t];
        if (c < NM2) ((float4*)sT2)[c] = ((const float4*)g_T2[0])[c];
    }
    __syncthreads();
    out[(size_t)b * 1024 + c] =
        do_pass<6, 23, 3>(sT3, sT2, xr, sy, W3s, W2s, W1s, U1s, c);

    // ---- passes 1..3: vector channels (shared unrolled body) ----
    for (int a = 0; a < 3; a++) {
        __syncthreads();
        {
            const float4* s3 = (const float4*)g_T3[a + 1];
            float4* d3 = (float4*)sT3;
            for (int t = c; t < NM3 * ST3 / 4; t += CDIM) d3[t] = s3[t];
            if (c < NM2) ((float4*)sT2)[c] = ((const float4*)g_T2[a + 1])[c];
        }
        __syncthreads();

        out[(size_t)b * 1024 + 256 + c * 3 + a] =
            do_pass<8, 30, 4>(sT3, sT2, xr, sy, W3v, W2v, W1v, U1v + a * NI, c);
    }
}

extern "C" void kernel_launch(void* const* d_in, const int* in_sizes, int n_in,
                              void* d_out, int out_size) {
    const float* x   = (const float*)d_in[0];
    const float* y   = (const float*)d_in[1];
    const float* U1s = (const float*)d_in[2];
    const float* U2s = (const float*)d_in[3];
    const float* U3s = (const float*)d_in[4];
    const float* U1v = (const float*)d_in[5];
    const float* U2v = (const float*)d_in[6];
    const float* U3v = (const float*)d_in[7];
    const float* W1s = (const float*)d_in[8];
    const float* W2s = (const float*)d_in[9];
    const float* W3s = (const float*)d_in[10];
    const float* W1v = (const float*)d_in[11];
    const float* W2v = (const float*)d_in[12];
    const float* W3v = (const float*)d_in[13];
    float* out = (float*)d_out;

    const int B = in_sizes[0] / (CDIM * NI);  // 2048

    const int total = 4 * NM3 * ST3 + 4 * NM2 * 4;
    precompute_kernel<<<(total + 255) / 256, 256>>>(U2s, U3s, U2v, U3v);
    sc_main_kernel<<<B, CDIM>>>(x, y, U1s, U1v, W1s, W2s, W3s, W1v, W2v, W3v, out);
}

// round 9
// speedup vs baseline: 3.9297x; 3.9297x over previous
#include <cuda_runtime.h>
#include <cuda_bf16.h>
#include <cstdint>

#define NI 9
#define NM3 165
#define NM2 45
#define ST3 32
#define CDIM 256
#define EDIM 10
#define NWORDS 112            // 224 bf16 = 112 u32 words per row
#define RSTRIDE 116           // row stride in u32 words (232 bf16) — ldmatrix conflict-free
#define SMB 59392             // A: 128*116*4
#define SMY 103936            // B: 2*48*116*4 = 44544
#define SMTOT 110080

__device__ __align__(16) float g_T3[4][NM3 * ST3];
__device__ __align__(16) float g_T2[4][NM2 * 4];
__device__ __align__(16) uint32_t g_H[CDIM * 2 * 48 * NWORDS];   // 11 MB, bf16-pair words

// ---------------- proven symmetrization precompute ----------------
__device__ __forceinline__ void decode3(int m, int& i, int& j, int& l) {
    int cnt = 0;
    for (int a = 0; a < NI; a++) for (int b = a; b < NI; b++) for (int c = b; c < NI; c++) {
        if (cnt == m) { i = a; j = b; l = c; return; } cnt++;
    }
    i = j = l = 0;
}
__device__ __forceinline__ void decode2(int m, int& i, int& j) {
    int cnt = 0;
    for (int a = 0; a < NI; a++) for (int b = a; b < NI; b++) {
        if (cnt == m) { i = a; j = b; return; } cnt++;
    }
    i = j = 0;
}
__global__ void precompute_kernel(const float* __restrict__ U2s, const float* __restrict__ U3s,
                                  const float* __restrict__ U2v, const float* __restrict__ U3v) {
    int t = blockIdx.x * blockDim.x + threadIdx.x;
    const int N3 = 4 * NM3 * ST3, N2 = 4 * NM2 * 4;
    if (t < N3) {
        int pass = t / (NM3 * ST3), r = t % (NM3 * ST3), m = r / ST3, k = r % ST3;
        int K = (pass == 0) ? 23 : 30;
        float val = 0.f;
        if (k < K) {
            int i, j, l; decode3(m, i, j, l);
            int pi[6] = { i, i, j, j, l, l }, pj[6] = { j, l, i, l, i, j }, pl[6] = { l, j, l, i, j, i };
            const float* base = (pass == 0) ? U3s : (U3v + (pass - 1) * (NI * NI * NI * 30));
            int codes[6];
            for (int q = 0; q < 6; q++) {
                int code = (pi[q] * NI + pj[q]) * NI + pl[q];
                bool dup = false;
                for (int u = 0; u < q; u++) if (codes[u] == code) dup = true;
                codes[q] = code;
                if (!dup) val += base[code * K + k];
            }
        }
        g_T3[pass][m * ST3 + k] = val;
    } else if (t < N3 + N2) {
        int u = t - N3, pass = u / (NM2 * 4), r = u % (NM2 * 4), m = r / 4, k = r % 4;
        int K = (pass == 0) ? 3 : 4;
        float val = 0.f;
        if (k < K) {
            int i, j; decode2(m, i, j);
            const float* base = (pass == 0) ? U2s : (U2v + (pass - 1) * (NI * NI * 4));
            val = base[(i * NI + j) * K + k];
            if (i != j) val += base[(j * NI + i) * K + k];
        }
        g_T2[pass][m * 4 + k] = val;
    }
}

// ---------------- H build: H[c][n=ch*12+e][m] = sum_k T_ch[m,k] W_ch[e,k,c] ----------------
__global__ void __launch_bounds__(192)
hbuild_kernel(const float* __restrict__ U1s, const float* __restrict__ U1v,
              const float* __restrict__ W1s, const float* __restrict__ W2s,
              const float* __restrict__ W3s, const float* __restrict__ W1v,
              const float* __restrict__ W2v, const float* __restrict__ W3v) {
    const int c = blockIdx.x >> 2, ch = blockIdx.x & 3;
    const int tid = threadIdx.x;
    __shared__ float sT3[NM3 * 33];
    __shared__ float sT2[NM2 * 4];
    __shared__ float sW3[12 * 30], sW2[12 * 4], sW1[12], sU1[9];

    const int K3 = ch ? 30 : 23, K2 = ch ? 4 : 3;
    const float* W3 = ch ? W3v : W3s;
    const float* W2 = ch ? W2v : W2s;
    const float* W1 = ch ? W1v : W1s;
    const float* U1 = ch ? (U1v + (ch - 1) * NI) : U1s;

    for (int idx = tid; idx < NM3 * 32; idx += 192)
        sT3[(idx >> 5) * 33 + (idx & 31)] = g_T3[ch][idx];
    for (int idx = tid; idx < NM2 * 4; idx += 192) sT2[idx] = g_T2[ch][idx];
    for (int idx = tid; idx < 12 * 30; idx += 192) {
        int e = idx / 30, kk = idx % 30;
        sW3[idx] = (e < EDIM && kk < K3) ? W3[(e * K3 + kk) * CDIM + c] : 0.f;
    }
    if (tid < 48) {
        int e = tid >> 2, kk = tid & 3;
        sW2[tid] = (e < EDIM && kk < K2) ? W2[(e * K2 + kk) * CDIM + c] : 0.f;
    }
    if (tid < 12) sW1[tid] = (tid < EDIM) ? W1[tid * CDIM + c] : 0.f;
    if (tid < 9) sU1[tid] = U1[tid];
    __syncthreads();

    const int e = tid / 16, t16 = tid % 16;
    const int n = ch * 12 + e;
    uint32_t* dstH = g_H + ((size_t)(c * 2 + 0) * 48 + n) * NWORDS;
    uint32_t* dstL = g_H + ((size_t)(c * 2 + 1) * 48 + n) * NWORDS;
    for (int it = 0; it < 7; it++) {
        int t = t16 + it * 16;   // word 0..111 -> monomials 2t, 2t+1
        float v[2];
#pragma unroll
        for (int h = 0; h < 2; h++) {
            int m = 2 * t + h;
            float s = 0.f;
            if (e < EDIM && m < 219) {
                if (m < 165) {
                    for (int kk = 0; kk < 30; kk++) s += sT3[m * 33 + kk] * sW3[e * 30 + kk];
                } else if (m < 210) {
                    int q = m - 165;
                    for (int kk = 0; kk < 4; kk++) s += sT2[q * 4 + kk] * sW2[e * 4 + kk];
                } else {
                    s = sU1[m - 210] * sW1[e];
                }
            }
            v[h] = s;
        }
        __nv_bfloat16 h0 = __float2bfloat16(v[0]), h1 = __float2bfloat16(v[1]);
        __nv_bfloat16 l0 = __float2bfloat16(v[0] - __bfloat162float(h0));
        __nv_bfloat16 l1 = __float2bfloat16(v[1] - __bfloat162float(h1));
        __nv_bfloat162 hh, ll; hh.x = h0; hh.y = h1; ll.x = l0; ll.y = l1;
        dstH[t] = *reinterpret_cast<uint32_t*>(&hh);
        dstL[t] = *reinterpret_cast<uint32_t*>(&ll);
    }
}

// ---------------- compile-time monomial maps for the A operand ----------------
__host__ __device__ constexpr int tri_p(int m) {
    int c = 0;
    for (int i = 0; i < 9; i++) for (int j = i; j < 9; j++) for (int l = j; l < 9; l++) {
        if (c == m) return i * 9 - i * (i - 1) / 2 + (j - i);
        c++;
    }
    return 0;
}
__host__ __device__ constexpr int tri_l(int m) {
    int c = 0;
    for (int i = 0; i < 9; i++) for (int j = i; j < 9; j++) for (int l = j; l < 9; l++) {
        if (c == m) return l;
        c++;
    }
    return 0;
}
template <int M>
__device__ __forceinline__ float elemv(const float* p, const float* xr) {
    if constexpr (M < 165) { constexpr int pi = tri_p(M), li = tri_l(M); return p[pi] * xr[li]; }
    else if constexpr (M < 210) return p[M - 165];
    else if constexpr (M < 219) return xr[M - 210];
    else return 0.f;
}
template <int T = 0>
__device__ __forceinline__ void build_row(uint32_t* dst, const float* p, const float* xr, bool lo) {
    if constexpr (T < NWORDS) {
        float v0 = elemv<2 * T>(p, xr), v1 = elemv<2 * T + 1>(p, xr);
        __nv_bfloat16 h0 = __float2bfloat16(v0), h1 = __float2bfloat16(v1);
        if (lo) {
            h0 = __float2bfloat16(v0 - __bfloat162float(h0));
            h1 = __float2bfloat16(v1 - __bfloat162float(h1));
        }
        __nv_bfloat162 hh; hh.x = h0; hh.y = h1;
        dst[T] = *reinterpret_cast<uint32_t*>(&hh);
        build_row<T + 1>(dst, p, xr, lo);
    }
}

// ---------------- mma helpers ----------------
__device__ __forceinline__ uint32_t s2u(const void* p) {
    uint32_t a;
    asm("{ .reg .u64 t; cvta.to.shared.u64 t, %1; cvt.u32.u64 %0, t; }" : "=r"(a) : "l"(p));
    return a;
}
#define LDSM4(r, addr) asm volatile( \
    "ldmatrix.sync.aligned.m8n8.x4.shared.b16 {%0,%1,%2,%3}, [%4];" \
    : "=r"((r)[0]), "=r"((r)[1]), "=r"((r)[2]), "=r"((r)[3]) : "r"(addr))
#define MMA16816(d, a, b0, b1) asm volatile( \
    "mma.sync.aligned.m16n8k16.row.col.f32.bf16.bf16.f32 " \
    "{%0,%1,%2,%3},{%4,%5,%6,%7},{%8,%9},{%0,%1,%2,%3};" \
    : "+f"((d)[0]), "+f"((d)[1]), "+f"((d)[2]), "+f"((d)[3]) \
    : "r"((a)[0]), "r"((a)[1]), "r"((a)[2]), "r"((a)[3]), "r"(b0), "r"(b1))

// ---------------- main kernel: CTA = (c, 128-row b tile) ----------------
__global__ void __launch_bounds__(128)
sc_mma_kernel(const float* __restrict__ x, const float* __restrict__ y,
              float* __restrict__ out, int ntile) {
    extern __shared__ __align__(16) char smem[];
    uint32_t* A32 = (uint32_t*)smem;
    uint32_t* B32 = (uint32_t*)(smem + SMB);
    float* sy = (float*)(smem + SMY);

    const int tid = threadIdx.x;
    const int lane = tid & 31, warp = tid >> 5;
    const int c = blockIdx.x / ntile;
    const int b0 = (blockIdx.x % ntile) << 7;
    const uint32_t sbA = s2u(A32), sbB = s2u(B32);

    // stage B (both splits) as uint4; dst word offsets divisible by 4 (116 = 4*29)
    {
        const uint4* src = (const uint4*)(g_H + (size_t)c * 2 * 48 * NWORDS);
        for (int t = tid; t < 2 * 48 * (NWORDS / 4); t += 128) {
            int row = t / (NWORDS / 4), q = t % (NWORDS / 4);
            *(uint4*)(B32 + row * RSTRIDE + q * 4) = src[t];
        }
        for (int t = tid; t < 128 * 12; t += 128) {
            int row = t / 12, e = t % 12;
            sy[t] = (e < EDIM) ? y[(size_t)(b0 + row) * EDIM + e] : 0.f;
        }
    }

    // per-thread monomials for row b0+tid
    float xr[NI], p[45];
    {
        const float* xp = x + ((size_t)(b0 + tid) * CDIM + c) * NI;
#pragma unroll
        for (int i = 0; i < NI; i++) xr[i] = xp[i];
        int pc = 0;
#pragma unroll
        for (int i = 0; i < NI; i++)
#pragma unroll
            for (int j = i; j < NI; j++) p[pc++] = xr[i] * xr[j];
    }
    build_row(A32 + tid * RSTRIDE, p, xr, false);   // A_hi
    __syncthreads();

    float acc[2][6][4];
#pragma unroll
    for (int a = 0; a < 2; a++)
#pragma unroll
        for (int b = 0; b < 6; b++)
#pragma unroll
            for (int d = 0; d < 4; d++) acc[a][b][d] = 0.f;

    const uint32_t aoff = ((uint32_t)(lane & 15)) * RSTRIDE * 4 + ((lane >> 4) << 4);
    const uint32_t boff = ((uint32_t)((lane & 7) + ((lane >> 4) << 3))) * RSTRIDE * 4 +
                          (((lane >> 3) & 1) << 4);

    // passes 1+2: A_hi x (B_hi, B_lo)
#pragma unroll 2
    for (int k = 0; k < 14; k++) {
        uint32_t af[2][4], bf[2][3][4];
#pragma unroll
        for (int mt = 0; mt < 2; mt++)
            LDSM4(af[mt], sbA + (warp * 32 + mt * 16) * RSTRIDE * 4 + k * 32 + aoff);
#pragma unroll
        for (int s = 0; s < 2; s++)
#pragma unroll
            for (int np = 0; np < 3; np++)
                LDSM4(bf[s][np], sbB + (s * 48 + np * 16) * RSTRIDE * 4 + k * 32 + boff);
#pragma unroll
        for (int mt = 0; mt < 2; mt++)
#pragma unroll
            for (int s = 0; s < 2; s++)
#pragma unroll
                for (int np = 0; np < 3; np++) {
                    MMA16816(acc[mt][np * 2 + 0], af[mt], bf[s][np][0], bf[s][np][1]);
                    MMA16816(acc[mt][np * 2 + 1], af[mt], bf[s][np][2], bf[s][np][3]);
                }
    }

    __syncthreads();
    build_row(A32 + tid * RSTRIDE, p, xr, true);    // A_lo
    __syncthreads();

    // pass 3: A_lo x B_hi
#pragma unroll 2
    for (int k = 0; k < 14; k++) {
        uint32_t af[2][4], bf[3][4];
#pragma unroll
        for (int mt = 0; mt < 2; mt++)
            LDSM4(af[mt], sbA + (warp * 32 + mt * 16) * RSTRIDE * 4 + k * 32 + aoff);
#pragma unroll
        for (int np = 0; np < 3; np++)
            LDSM4(bf[np], sbB + (np * 16) * RSTRIDE * 4 + k * 32 + boff);
#pragma unroll
        for (int mt = 0; mt < 2; mt++)
#pragma unroll
            for (int np = 0; np < 3; np++) {
                MMA16816(acc[mt][np * 2 + 0], af[mt], bf[np][0], bf[np][1]);
                MMA16816(acc[mt][np * 2 + 1], af[mt], bf[np][2], bf[np][3]);
            }
    }

    // epilogue: scale by y, reduce 12 e-cols per channel across the 4 tig lanes
    const int g = lane >> 2, tig = lane & 3;
    float res[2][2][4];
#pragma unroll
    for (int a = 0; a < 2; a++)
#pragma unroll
        for (int h = 0; h < 2; h++)
#pragma unroll
            for (int d = 0; d < 4; d++) res[a][h][d] = 0.f;
#pragma unroll
    for (int mt = 0; mt < 2; mt++) {
        const int r0 = warp * 32 + mt * 16 + g;
#pragma unroll
        for (int nt = 0; nt < 6; nt++) {
            int c0 = nt * 8 + tig * 2, c1 = c0 + 1;
            int e0 = c0 % 12, ch0 = c0 / 12;
            int e1 = c1 % 12, ch1 = c1 / 12;
            res[mt][0][ch0] += acc[mt][nt][0] * sy[r0 * 12 + e0];
            res[mt][0][ch1] += acc[mt][nt][1] * sy[r0 * 12 + e1];
            res[mt][1][ch0] += acc[mt][nt][2] * sy[(r0 + 8) * 12 + e0];
            res[mt][1][ch1] += acc[mt][nt][3] * sy[(r0 + 8) * 12 + e1];
        }
    }
#pragma unroll
    for (int d = 1; d <= 2; d <<= 1)
#pragma unroll
        for (int a = 0; a < 2; a++)
#pragma unroll
            for (int h = 0; h < 2; h++)
#pragma unroll
                for (int q = 0; q < 4; q++)
                    res[a][h][q] += __shfl_xor_sync(0xffffffffu, res[a][h][q], d);

    if (tig == 0) {
#pragma unroll
        for (int mt = 0; mt < 2; mt++)
#pragma unroll
            for (int h = 0; h < 2; h++) {
                size_t b = (size_t)(b0 + warp * 32 + mt * 16 + g + h * 8);
                out[b * 1024 + c] = res[mt][h][0];
                out[b * 1024 + 256 + c * 3 + 0] = res[mt][h][1];
                out[b * 1024 + 256 + c * 3 + 1] = res[mt][h][2];
                out[b * 1024 + 256 + c * 3 + 2] = res[mt][h][3];
            }
    }
}

extern "C" void kernel_launch(void* const* d_in, const int* in_sizes, int n_in,
                              void* d_out, int out_size) {
    const float* x   = (const float*)d_in[0];
    const float* y   = (const float*)d_in[1];
    const float* U1s = (const float*)d_in[2];
    const float* U2s = (const float*)d_in[3];
    const float* U3s = (const float*)d_in[4];
    const float* U1v = (const float*)d_in[5];
    const float* U2v = (const float*)d_in[6];
    const float* U3v = (const float*)d_in[7];
    const float* W1s = (const float*)d_in[8];
    const float* W2s = (const float*)d_in[9];
    const float* W3s = (const float*)d_in[10];
    const float* W1v = (const float*)d_in[11];
    const float* W2v = (const float*)d_in[12];
    const float* W3v = (const float*)d_in[13];
    float* out = (float*)d_out;

    const int B = in_sizes[0] / (CDIM * NI);  // 2048
    const int ntile = B / 128;

    cudaFuncSetAttribute(sc_mma_kernel, cudaFuncAttributeMaxDynamicSharedMemorySize, SMTOT);

    const int total = 4 * NM3 * ST3 + 4 * NM2 * 4;
    precompute_kernel<<<(total + 255) / 256, 256>>>(U2s, U3s, U2v, U3v);
    hbuild_kernel<<<CDIM * 4, 192>>>(U1s, U1v, W1s, W2s, W3s, W1v, W2v, W3v);
    sc_mma_kernel<<<CDIM * ntile, 128, SMTOT>>>(x, y, out, ntile);
}

// round 10
// speedup vs baseline: 4.0615x; 1.0335x over previous
#include <cuda_runtime.h>
#include <cuda_bf16.h>
#include <cstdint>

#define NI 9
#define NM3 165
#define NM2 45
#define ST3 32
#define CDIM 256
#define EDIM 10
#define NWORDS 112            // 224 bf16 = 112 u32 words per row
#define RSTRIDE 116           // row stride in u32 words (232 bf16) — ldmatrix conflict-free
#define SMB 59392             // A: 128*116*4
#define SMY 103936            // B: 2*48*116*4 = 44544
#define SMTOT 110080

__device__ __align__(16) float g_T3[4][NM3 * ST3];
__device__ __align__(16) float g_T2[4][NM2 * 4];
__device__ __align__(16) uint32_t g_H[CDIM * 2 * 48 * NWORDS];   // 11 MB, bf16-pair words

// ---------------- proven symmetrization precompute ----------------
__device__ __forceinline__ void decode3(int m, int& i, int& j, int& l) {
    int cnt = 0;
    for (int a = 0; a < NI; a++) for (int b = a; b < NI; b++) for (int c = b; c < NI; c++) {
        if (cnt == m) { i = a; j = b; l = c; return; } cnt++;
    }
    i = j = l = 0;
}
__device__ __forceinline__ void decode2(int m, int& i, int& j) {
    int cnt = 0;
    for (int a = 0; a < NI; a++) for (int b = a; b < NI; b++) {
        if (cnt == m) { i = a; j = b; return; } cnt++;
    }
    i = j = 0;
}
__global__ void precompute_kernel(const float* __restrict__ U2s, const float* __restrict__ U3s,
                                  const float* __restrict__ U2v, const float* __restrict__ U3v) {
    int t = blockIdx.x * blockDim.x + threadIdx.x;
    const int N3 = 4 * NM3 * ST3, N2 = 4 * NM2 * 4;
    if (t < N3) {
        int pass = t / (NM3 * ST3), r = t % (NM3 * ST3), m = r / ST3, k = r % ST3;
        int K = (pass == 0) ? 23 : 30;
        float val = 0.f;
        if (k < K) {
            int i, j, l; decode3(m, i, j, l);
            int pi[6] = { i, i, j, j, l, l }, pj[6] = { j, l, i, l, i, j }, pl[6] = { l, j, l, i, j, i };
            const float* base = (pass == 0) ? U3s : (U3v + (pass - 1) * (NI * NI * NI * 30));
            int codes[6];
            for (int q = 0; q < 6; q++) {
                int code = (pi[q] * NI + pj[q]) * NI + pl[q];
                bool dup = false;
                for (int u = 0; u < q; u++) if (codes[u] == code) dup = true;
                codes[q] = code;
                if (!dup) val += base[code * K + k];
            }
        }
        g_T3[pass][m * ST3 + k] = val;
    } else if (t < N3 + N2) {
        int u = t - N3, pass = u / (NM2 * 4), r = u % (NM2 * 4), m = r / 4, k = r % 4;
        int K = (pass == 0) ? 3 : 4;
        float val = 0.f;
        if (k < K) {
            int i, j; decode2(m, i, j);
            const float* base = (pass == 0) ? U2s : (U2v + (pass - 1) * (NI * NI * 4));
            val = base[(i * NI + j) * K + k];
            if (i != j) val += base[(j * NI + i) * K + k];
        }
        g_T2[pass][m * 4 + k] = val;
    }
}

// ---------------- H build ----------------
__global__ void __launch_bounds__(192)
hbuild_kernel(const float* __restrict__ U1s, const float* __restrict__ U1v,
              const float* __restrict__ W1s, const float* __restrict__ W2s,
              const float* __restrict__ W3s, const float* __restrict__ W1v,
              const float* __restrict__ W2v, const float* __restrict__ W3v) {
    const int c = blockIdx.x >> 2, ch = blockIdx.x & 3;
    const int tid = threadIdx.x;
    __shared__ float sT3[NM3 * 33];
    __shared__ float sT2[NM2 * 4];
    __shared__ float sW3[12 * 30], sW2[12 * 4], sW1[12], sU1[9];

    const int K3 = ch ? 30 : 23, K2 = ch ? 4 : 3;
    const float* W3 = ch ? W3v : W3s;
    const float* W2 = ch ? W2v : W2s;
    const float* W1 = ch ? W1v : W1s;
    const float* U1 = ch ? (U1v + (ch - 1) * NI) : U1s;

    for (int idx = tid; idx < NM3 * 32; idx += 192)
        sT3[(idx >> 5) * 33 + (idx & 31)] = g_T3[ch][idx];
    for (int idx = tid; idx < NM2 * 4; idx += 192) sT2[idx] = g_T2[ch][idx];
    for (int idx = tid; idx < 12 * 30; idx += 192) {
        int e = idx / 30, kk = idx % 30;
        sW3[idx] = (e < EDIM && kk < K3) ? W3[(e * K3 + kk) * CDIM + c] : 0.f;
    }
    if (tid < 48) {
        int e = tid >> 2, kk = tid & 3;
        sW2[tid] = (e < EDIM && kk < K2) ? W2[(e * K2 + kk) * CDIM + c] : 0.f;
    }
    if (tid < 12) sW1[tid] = (tid < EDIM) ? W1[tid * CDIM + c] : 0.f;
    if (tid < 9) sU1[tid] = U1[tid];
    __syncthreads();

    const int e = tid / 16, t16 = tid % 16;
    const int n = ch * 12 + e;
    uint32_t* dstH = g_H + ((size_t)(c * 2 + 0) * 48 + n) * NWORDS;
    uint32_t* dstL = g_H + ((size_t)(c * 2 + 1) * 48 + n) * NWORDS;
    for (int it = 0; it < 7; it++) {
        int t = t16 + it * 16;
        float v[2];
#pragma unroll
        for (int h = 0; h < 2; h++) {
            int m = 2 * t + h;
            float s = 0.f;
            if (e < EDIM && m < 219) {
                if (m < 165) {
                    for (int kk = 0; kk < 30; kk++) s += sT3[m * 33 + kk] * sW3[e * 30 + kk];
                } else if (m < 210) {
                    int q = m - 165;
                    for (int kk = 0; kk < 4; kk++) s += sT2[q * 4 + kk] * sW2[e * 4 + kk];
                } else {
                    s = sU1[m - 210] * sW1[e];
                }
            }
            v[h] = s;
        }
        __nv_bfloat16 h0 = __float2bfloat16(v[0]), h1 = __float2bfloat16(v[1]);
        __nv_bfloat16 l0 = __float2bfloat16(v[0] - __bfloat162float(h0));
        __nv_bfloat16 l1 = __float2bfloat16(v[1] - __bfloat162float(h1));
        __nv_bfloat162 hh, ll; hh.x = h0; hh.y = h1; ll.x = l0; ll.y = l1;
        dstH[t] = *reinterpret_cast<uint32_t*>(&hh);
        dstL[t] = *reinterpret_cast<uint32_t*>(&ll);
    }
}

// ---------------- compile-time monomial maps for the A operand ----------------
__host__ __device__ constexpr int tri_p(int m) {
    int c = 0;
    for (int i = 0; i < 9; i++) for (int j = i; j < 9; j++) for (int l = j; l < 9; l++) {
        if (c == m) return i * 9 - i * (i - 1) / 2 + (j - i);
        c++;
    }
    return 0;
}
__host__ __device__ constexpr int tri_l(int m) {
    int c = 0;
    for (int i = 0; i < 9; i++) for (int j = i; j < 9; j++) for (int l = j; l < 9; l++) {
        if (c == m) return l;
        c++;
    }
    return 0;
}
template <int M>
__device__ __forceinline__ float elemv(const float* p, const float* xr) {
    if constexpr (M < 165) { constexpr int pi = tri_p(M), li = tri_l(M); return p[pi] * xr[li]; }
    else if constexpr (M < 210) return p[M - 165];
    else if constexpr (M < 219) return xr[M - 210];
    else return 0.f;
}

// one-instruction bf16x2 pack: low half = v0, high half = v1
__device__ __forceinline__ uint32_t pack_bf(float v0, float v1) {
    uint32_t w;
    asm("cvt.rn.bf16x2.f32 %0, %1, %2;" : "=r"(w) : "f"(v1), "f"(v0));
    return w;
}
// lo-split word: residuals of the rn-bf16 hi split, recovered via bit ops
__device__ __forceinline__ uint32_t pack_bf_lo(float v0, float v1) {
    uint32_t h = pack_bf(v0, v1);
    float f0 = __uint_as_float(h << 16);
    float f1 = __uint_as_float(h & 0xFFFF0000u);
    return pack_bf(v0 - f0, v1 - f1);
}

template <int G = 0>
__device__ __forceinline__ void build_hi(uint4* dst, const float* p, const float* xr) {
    if constexpr (G < 28) {
        uint4 w;
        w.x = pack_bf(elemv<8 * G + 0>(p, xr), elemv<8 * G + 1>(p, xr));
        w.y = pack_bf(elemv<8 * G + 2>(p, xr), elemv<8 * G + 3>(p, xr));
        w.z = pack_bf(elemv<8 * G + 4>(p, xr), elemv<8 * G + 5>(p, xr));
        w.w = pack_bf(elemv<8 * G + 6>(p, xr), elemv<8 * G + 7>(p, xr));
        dst[G] = w;
        build_hi<G + 1>(dst, p, xr);
    }
}
template <int G = 0>
__device__ __forceinline__ void build_lo(uint4* dst, const float* p, const float* xr) {
    if constexpr (G < 28) {
        uint4 w;
        w.x = pack_bf_lo(elemv<8 * G + 0>(p, xr), elemv<8 * G + 1>(p, xr));
        w.y = pack_bf_lo(elemv<8 * G + 2>(p, xr), elemv<8 * G + 3>(p, xr));
        w.z = pack_bf_lo(elemv<8 * G + 4>(p, xr), elemv<8 * G + 5>(p, xr));
        w.w = pack_bf_lo(elemv<8 * G + 6>(p, xr), elemv<8 * G + 7>(p, xr));
        dst[G] = w;
        build_lo<G + 1>(dst, p, xr);
    }
}

// ---------------- mma helpers ----------------
__device__ __forceinline__ uint32_t s2u(const void* p) {
    uint32_t a;
    asm("{ .reg .u64 t; cvta.to.shared.u64 t, %1; cvt.u32.u64 %0, t; }" : "=r"(a) : "l"(p));
    return a;
}
#define LDSM4(r, addr) asm volatile( \
    "ldmatrix.sync.aligned.m8n8.x4.shared.b16 {%0,%1,%2,%3}, [%4];" \
    : "=r"((r)[0]), "=r"((r)[1]), "=r"((r)[2]), "=r"((r)[3]) : "r"(addr))
#define MMA16816(d, a, b0, b1) asm volatile( \
    "mma.sync.aligned.m16n8k16.row.col.f32.bf16.bf16.f32 " \
    "{%0,%1,%2,%3},{%4,%5,%6,%7},{%8,%9},{%0,%1,%2,%3};" \
    : "+f"((d)[0]), "+f"((d)[1]), "+f"((d)[2]), "+f"((d)[3]) \
    : "r"((a)[0]), "r"((a)[1]), "r"((a)[2]), "r"((a)[3]), "r"(b0), "r"(b1))

// ---------------- main kernel: CTA = (b-tile = blockIdx.x, c = blockIdx.y) ----------------
__global__ void __launch_bounds__(128)
sc_mma_kernel(const float* __restrict__ x, const float* __restrict__ y,
              float* __restrict__ out) {
    extern __shared__ __align__(16) char smem[];
    uint32_t* A32 = (uint32_t*)smem;
    uint32_t* B32 = (uint32_t*)(smem + SMB);
    float* sy = (float*)(smem + SMY);

    const int tid = threadIdx.x;
    const int lane = tid & 31, warp = tid >> 5;
    const int c = blockIdx.y;
    const int b0 = blockIdx.x << 7;
    const uint32_t sbA = s2u(A32), sbB = s2u(B32);

    // stage B (both splits) and y tile
    {
        const uint4* src = (const uint4*)(g_H + (size_t)c * 2 * 48 * NWORDS);
        for (int t = tid; t < 2 * 48 * (NWORDS / 4); t += 128) {
            int row = t / (NWORDS / 4), q = t % (NWORDS / 4);
            *(uint4*)(B32 + row * RSTRIDE + q * 4) = src[t];
        }
        for (int t = tid; t < 128 * 12; t += 128) {
            int row = t / 12, e = t % 12;
            sy[t] = (e < EDIM) ? y[(size_t)(b0 + row) * EDIM + e] : 0.f;
        }
    }

    // per-thread monomials for row b0+tid
    float xr[NI], p[45];
    {
        const float* xp = x + ((size_t)(b0 + tid) * CDIM + c) * NI;
#pragma unroll
        for (int i = 0; i < NI; i++) xr[i] = xp[i];
        int pc = 0;
#pragma unroll
        for (int i = 0; i < NI; i++)
#pragma unroll
            for (int j = i; j < NI; j++) p[pc++] = xr[i] * xr[j];
    }
    build_hi((uint4*)(A32 + tid * RSTRIDE), p, xr);
    __syncthreads();

    float acc[2][6][4];
#pragma unroll
    for (int a = 0; a < 2; a++)
#pragma unroll
        for (int b = 0; b < 6; b++)
#pragma unroll
            for (int d = 0; d < 4; d++) acc[a][b][d] = 0.f;

    const uint32_t aoff = ((uint32_t)(lane & 15)) * RSTRIDE * 4 + ((lane >> 4) << 4);
    const uint32_t boff = ((uint32_t)((lane & 7) + ((lane >> 4) << 3))) * RSTRIDE * 4 +
                          (((lane >> 3) & 1) << 4);

    // passes 1+2: A_hi x (B_hi, B_lo)
#pragma unroll 2
    for (int k = 0; k < 14; k++) {
        uint32_t af[2][4], bf[2][3][4];
#pragma unroll
        for (int mt = 0; mt < 2; mt++)
            LDSM4(af[mt], sbA + (warp * 32 + mt * 16) * RSTRIDE * 4 + k * 32 + aoff);
#pragma unroll
        for (int s = 0; s < 2; s++)
#pragma unroll
            for (int np = 0; np < 3; np++)
                LDSM4(bf[s][np], sbB + (s * 48 + np * 16) * RSTRIDE * 4 + k * 32 + boff);
#pragma unroll
        for (int mt = 0; mt < 2; mt++)
#pragma unroll
            for (int s = 0; s < 2; s++)
#pragma unroll
                for (int np = 0; np < 3; np++) {
                    MMA16816(acc[mt][np * 2 + 0], af[mt], bf[s][np][0], bf[s][np][1]);
                    MMA16816(acc[mt][np * 2 + 1], af[mt], bf[s][np][2], bf[s][np][3]);
                }
    }

    __syncthreads();
    build_lo((uint4*)(A32 + tid * RSTRIDE), p, xr);
    __syncthreads();

    // pass 3: A_lo x B_hi
#pragma unroll 2
    for (int k = 0; k < 14; k++) {
        uint32_t af[2][4], bf[3][4];
#pragma unroll
        for (int mt = 0; mt < 2; mt++)
            LDSM4(af[mt], sbA + (warp * 32 + mt * 16) * RSTRIDE * 4 + k * 32 + aoff);
#pragma unroll
        for (int np = 0; np < 3; np++)
            LDSM4(bf[np], sbB + (np * 16) * RSTRIDE * 4 + k * 32 + boff);
#pragma unroll
        for (int mt = 0; mt < 2; mt++)
#pragma unroll
            for (int np = 0; np < 3; np++) {
                MMA16816(acc[mt][np * 2 + 0], af[mt], bf[np][0], bf[np][1]);
                MMA16816(acc[mt][np * 2 + 1], af[mt], bf[np][2], bf[np][3]);
            }
    }

    // epilogue: scale by y, reduce 12 e-cols per channel across the 4 tig lanes
    const int g = lane >> 2, tig = lane & 3;
    float res[2][2][4];
#pragma unroll
    for (int a = 0; a < 2; a++)
#pragma unroll
        for (int h = 0; h < 2; h++)
#pragma unroll
            for (int d = 0; d < 4; d++) res[a][h][d] = 0.f;
#pragma unroll
    for (int mt = 0; mt < 2; mt++) {
        const int r0 = warp * 32 + mt * 16 + g;
#pragma unroll
        for (int nt = 0; nt < 6; nt++) {
            int c0 = nt * 8 + tig * 2, c1 = c0 + 1;
            int e0 = c0 % 12, ch0 = c0 / 12;
            int e1 = c1 % 12, ch1 = c1 / 12;
            res[mt][0][ch0] += acc[mt][nt][0] * sy[r0 * 12 + e0];
            res[mt][0][ch1] += acc[mt][nt][1] * sy[r0 * 12 + e1];
            res[mt][1][ch0] += acc[mt][nt][2] * sy[(r0 + 8) * 12 + e0];
            res[mt][1][ch1] += acc[mt][nt][3] * sy[(r0 + 8) * 12 + e1];
        }
    }
#pragma unroll
    for (int d = 1; d <= 2; d <<= 1)
#pragma unroll
        for (int a = 0; a < 2; a++)
#pragma unroll
            for (int h = 0; h < 2; h++)
#pragma unroll
                for (int q = 0; q < 4; q++)
                    res[a][h][q] += __shfl_xor_sync(0xffffffffu, res[a][h][q], d);

    if (tig == 0) {
#pragma unroll
        for (int mt = 0; mt < 2; mt++)
#pragma unroll
            for (int h = 0; h < 2; h++) {
                size_t b = (size_t)(b0 + warp * 32 + mt * 16 + g + h * 8);
                out[b * 1024 + c] = res[mt][h][0];
                out[b * 1024 + 256 + c * 3 + 0] = res[mt][h][1];
                out[b * 1024 + 256 + c * 3 + 1] = res[mt][h][2];
                out[b * 1024 + 256 + c * 3 + 2] = res[mt][h][3];
            }
    }
}

extern "C" void kernel_launch(void* const* d_in, const int* in_sizes, int n_in,
                              void* d_out, int out_size) {
    const float* x   = (const float*)d_in[0];
    const float* y   = (const float*)d_in[1];
    const float* U1s = (const float*)d_in[2];
    const float* U2s = (const float*)d_in[3];
    const float* U3s = (const float*)d_in[4];
    const float* U1v = (const float*)d_in[5];
    const float* U2v = (const float*)d_in[6];
    const float* U3v = (const float*)d_in[7];
    const float* W1s = (const float*)d_in[8];
    const float* W2s = (const float*)d_in[9];
    const float* W3s = (const float*)d_in[10];
    const float* W1v = (const float*)d_in[11];
    const float* W2v = (const float*)d_in[12];
    const float* W3v = (const float*)d_in[13];
    float* out = (float*)d_out;

    const int B = in_sizes[0] / (CDIM * NI);  // 2048
    const int ntile = B / 128;

    cudaFuncSetAttribute(sc_mma_kernel, cudaFuncAttributeMaxDynamicSharedMemorySize, SMTOT);

    const int total = 4 * NM3 * ST3 + 4 * NM2 * 4;
    precompute_kernel<<<(total + 255) / 256, 256>>>(U2s, U3s, U2v, U3v);
    hbuild_kernel<<<CDIM * 4, 192>>>(U1s, U1v, W1s, W2s, W3s, W1v, W2v, W3v);
    sc_mma_kernel<<<dim3(ntile, CDIM), 128, SMTOT>>>(x, y, out);
}